// round 4
// baseline (speedup 1.0000x reference)
#include <cuda_runtime.h>
#include <cstdint>

// ROI pooling (bilinear, half-pixel centers, clamped to crop).
//   img:  (1, 1024, 1024, 256) float32, NHWC
//   rois: (1, 300, 4) float32 (x0, y0, w, h) -> int
//   out:  (1, 300, 7, 7, 256) float32
//
// R4: cp.async (LDGSTS) into smem instead of register-destination LDG.
// 8 in-flight 16B copies per thread with ~30 regs -> high occupancy AND
// high MLP simultaneously (R1-R3 showed occ x MLP was the invariant).
// Each thread reads back only the smem it wrote, so wait_group 0 suffices
// (no __syncthreads).

#define POOL 7
#define IMG_W 1024
#define C4 64          // 256 channels / 4 floats each

__device__ __forceinline__ void cp16(void* smem_dst, const float4* gsrc) {
    uint32_t d = (uint32_t)__cvta_generic_to_shared(smem_dst);
    asm volatile("cp.async.cg.shared.global [%0], [%1], 16;\n"
                 :: "r"(d), "l"(gsrc));
}

__global__ __launch_bounds__(256) void roi_pool_kernel(
    const float4* __restrict__ img4,   // (H*W, 64) float4
    const float4* __restrict__ rois4,  // (300) float4 = (x0,y0,w,h)
    float4* __restrict__ out4)         // (300*49, 64) float4
{
    __shared__ float4 buf[4][2][4][64];   // [ty][pos][corner][c] = 32 KB

    const int roi = blockIdx.y;
    const int px  = blockIdx.x;        // 0..6
    const int ty  = threadIdx.y;       // 0..3
    const int c   = threadIdx.x;       // 0..63

    const float4 rp = __ldg(rois4 + roi);
    const int x0 = (int)rp.x;
    const int y0 = (int)rp.y;
    const int w  = (int)rp.z;
    const int h  = (int)rp.w;

    // x coords (shared across py for this block)
    float cx = ((float)px + 0.5f) * ((float)w / (float)POOL) - 0.5f;
    cx = fminf(fmaxf(cx, 0.0f), (float)w - 1.0f);
    const int xlo = (int)cx;
    const int xhi = min(xlo + 1, w - 1);
    const float fx = cx - (float)xlo;

    const float hs   = (float)h / (float)POOL;
    const float hmax = (float)h - 1.0f;

    const int py0 = ty;            // 0..3
    const int py1 = ty + 4;        // valid if < 7
    const bool has1 = (py1 < POOL);

    float cy0 = ((float)py0 + 0.5f) * hs - 0.5f;
    cy0 = fminf(fmaxf(cy0, 0.0f), hmax);
    const int ylo0 = (int)cy0;
    const int yhi0 = min(ylo0 + 1, h - 1);
    const float fy0 = cy0 - (float)ylo0;

    float cy1 = ((float)py1 + 0.5f) * hs - 0.5f;
    cy1 = fminf(fmaxf(cy1, 0.0f), hmax);
    const int ylo1 = (int)cy1;
    const int yhi1 = min(ylo1 + 1, h - 1);
    const float fy1 = cy1 - (float)ylo1;

    // Offsets in float4 units fit in 32 bits (max 2^26).
    const unsigned colL = (unsigned)(x0 + xlo) * C4 + c;
    const unsigned colR = (unsigned)(x0 + xhi) * C4 + c;
    const unsigned rlo0 = (unsigned)(y0 + ylo0) * (IMG_W * C4);
    const unsigned rhi0 = (unsigned)(y0 + yhi0) * (IMG_W * C4);
    const unsigned rlo1 = (unsigned)(y0 + ylo1) * (IMG_W * C4);
    const unsigned rhi1 = (unsigned)(y0 + yhi1) * (IMG_W * C4);

    // Fire all async copies (no destination registers consumed)
    cp16(&buf[ty][0][0][c], img4 + rlo0 + colL);
    cp16(&buf[ty][0][1][c], img4 + rlo0 + colR);
    cp16(&buf[ty][0][2][c], img4 + rhi0 + colL);
    cp16(&buf[ty][0][3][c], img4 + rhi0 + colR);
    if (has1) {
        cp16(&buf[ty][1][0][c], img4 + rlo1 + colL);
        cp16(&buf[ty][1][1][c], img4 + rlo1 + colR);
        cp16(&buf[ty][1][2][c], img4 + rhi1 + colL);
        cp16(&buf[ty][1][3][c], img4 + rhi1 + colR);
    }
    asm volatile("cp.async.commit_group;\n" ::: "memory");
    asm volatile("cp.async.wait_group 0;\n" ::: "memory");

    const float gx = 1.0f - fx;
    const unsigned obase = (unsigned)roi * (POOL * POOL) * C4 + c;

    {
        const float w00 = (1.0f - fy0) * gx, w01 = (1.0f - fy0) * fx;
        const float w10 = fy0 * gx,          w11 = fy0 * fx;
        const float4 v00 = buf[ty][0][0][c];
        const float4 v01 = buf[ty][0][1][c];
        const float4 v10 = buf[ty][0][2][c];
        const float4 v11 = buf[ty][0][3][c];
        float4 o;
        o.x = v00.x * w00 + v01.x * w01 + v10.x * w10 + v11.x * w11;
        o.y = v00.y * w00 + v01.y * w01 + v10.y * w10 + v11.y * w11;
        o.z = v00.z * w00 + v01.z * w01 + v10.z * w10 + v11.z * w11;
        o.w = v00.w * w00 + v01.w * w01 + v10.w * w10 + v11.w * w11;
        __stcs(out4 + obase + (unsigned)(py0 * POOL + px) * C4, o);
    }

    if (has1) {
        const float w00 = (1.0f - fy1) * gx, w01 = (1.0f - fy1) * fx;
        const float w10 = fy1 * gx,          w11 = fy1 * fx;
        const float4 v00 = buf[ty][1][0][c];
        const float4 v01 = buf[ty][1][1][c];
        const float4 v10 = buf[ty][1][2][c];
        const float4 v11 = buf[ty][1][3][c];
        float4 o;
        o.x = v00.x * w00 + v01.x * w01 + v10.x * w10 + v11.x * w11;
        o.y = v00.y * w00 + v01.y * w01 + v10.y * w10 + v11.y * w11;
        o.z = v00.z * w00 + v01.z * w01 + v10.z * w10 + v11.z * w11;
        o.w = v00.w * w00 + v01.w * w01 + v10.w * w10 + v11.w * w11;
        __stcs(out4 + obase + (unsigned)(py1 * POOL + px) * C4, o);
    }
}

extern "C" void kernel_launch(void* const* d_in, const int* in_sizes, int n_in,
                              void* d_out, int out_size)
{
    const float4* img4  = (const float4*)d_in[0];
    const float4* rois4 = (const float4*)d_in[1];
    float4* o4 = (float4*)d_out;

    dim3 block(64, 4, 1);       // 64 float4-lanes x 4 py-slots
    dim3 grid(POOL, 300, 1);    // px x roi
    roi_pool_kernel<<<grid, block>>>(img4, rois4, o4);
}